// round 12
// baseline (speedup 1.0000x reference)
#include <cuda_runtime.h>
#include <cuda_bf16.h>
#include <cstdint>

// Problem constants
#define BC    768
#define NH    12
#define HD    64
#define SEQ   197
#define BATCH 64
#define M_TOT (BATCH*SEQ)     // 12608
#define QKV_N (3*BC)          // 2304
#define KDIM  768

// ---------------- scratch (static __device__, allocation-free) -------------
__device__ float g_q[BATCH*NH*SEQ*HD];
__device__ float g_k[BATCH*NH*SEQ*HD];
__device__ float g_v[BATCH*NH*SEQ*HD];

__device__ __nv_bfloat16 s_xh[M_TOT*BC],  s_xl[M_TOT*BC];
__device__ __nv_bfloat16 s_qwh[QKV_N*BC], s_qwl[QKV_N*BC];
__device__ __nv_bfloat16 s_pwh[BC*BC],    s_pwl[BC*BC];
__device__ __nv_bfloat16 s_oh[M_TOT*BC],  s_ol[M_TOT*BC];

// ---------------------------------------------------------------------------
// fp32 -> (hi,lo) bf16 split.  DST: 0=x, 1=qkv_weight, 2=proj_weight
// ---------------------------------------------------------------------------
template<int DST>
__global__ void split_kernel(const float4* __restrict__ in, int n4)
{
    __nv_bfloat16* hi = (DST == 0) ? s_xh : (DST == 1) ? s_qwh : s_pwh;
    __nv_bfloat16* lo = (DST == 0) ? s_xl : (DST == 1) ? s_qwl : s_pwl;

    int i = blockIdx.x * blockDim.x + threadIdx.x;
    if (i >= n4) return;
    float4 v = in[i];
    float f[4] = {v.x, v.y, v.z, v.w};
    __nv_bfloat16 h[4], l[4];
    #pragma unroll
    for (int j = 0; j < 4; ++j) {
        h[j] = __float2bfloat16_rn(f[j]);
        l[j] = __float2bfloat16_rn(f[j] - __bfloat162float(h[j]));
    }
    __nv_bfloat162* hp = (__nv_bfloat162*)hi;
    __nv_bfloat162* lp = (__nv_bfloat162*)lo;
    hp[i*2+0] = __nv_bfloat162(h[0], h[1]);
    hp[i*2+1] = __nv_bfloat162(h[2], h[3]);
    lp[i*2+0] = __nv_bfloat162(l[0], l[1]);
    lp[i*2+1] = __nv_bfloat162(l[2], l[3]);
}

// ---------------------------------------------------------------------------
// PTX helpers
// ---------------------------------------------------------------------------
__device__ __forceinline__ void ldsm4(uint32_t& r0, uint32_t& r1,
                                      uint32_t& r2, uint32_t& r3, uint32_t a)
{
    asm volatile("ldmatrix.sync.aligned.m8n8.x4.shared.b16 {%0,%1,%2,%3},[%4];"
                 : "=r"(r0), "=r"(r1), "=r"(r2), "=r"(r3) : "r"(a));
}
__device__ __forceinline__ void mma16816(float& c0, float& c1, float& c2, float& c3,
                                         uint32_t a0, uint32_t a1, uint32_t a2, uint32_t a3,
                                         uint32_t b0, uint32_t b1)
{
    asm volatile("mma.sync.aligned.m16n8k16.row.col.f32.bf16.bf16.f32 "
                 "{%0,%1,%2,%3},{%4,%5,%6,%7},{%8,%9},{%0,%1,%2,%3};"
                 : "+f"(c0), "+f"(c1), "+f"(c2), "+f"(c3)
                 : "r"(a0), "r"(a1), "r"(a2), "r"(a3), "r"(b0), "r"(b1));
}
__device__ __forceinline__ void cp16(uint32_t d, const void* s)
{
    asm volatile("cp.async.cg.shared.global [%0],[%1],16;" :: "r"(d), "l"(s));
}
__device__ __forceinline__ void cp_commit() { asm volatile("cp.async.commit_group;"); }
template<int N>
__device__ __forceinline__ void cp_wait() { asm volatile("cp.async.wait_group %0;" :: "n"(N)); }

__device__ __forceinline__ uint32_t pack_bf2(float x, float y)
{
    __nv_bfloat162 t(__float2bfloat16_rn(x), __float2bfloat16_rn(y));
    return *(uint32_t*)&t;
}

// ---------------------------------------------------------------------------
// bf16x3 tensor-core GEMM, 512 threads, tile 128x256, BKT=64 (rows = 128B,
// pitch 144B -> conflict-free ldsm). 12 k-steps (half the barriers of R8),
// loads per output /1.5. Warp tile 32x64 (4x4 warp grid). Same MMA order
// per accumulator as R8 -> bit-identical results.
// MODE 0: A=s_x*, B=s_qw*, scatter -> g_q/g_k/g_v    MODE 1: A=s_o*, B=s_pw*
// ---------------------------------------------------------------------------
#define GBM 128
#define GBN 256
#define GBKT 64
#define GPCH 144
#define A_TILE_B (128*GPCH)            // 18432
#define B_TILE_B (256*GPCH)            // 36864
#define OFF_AH 0
#define OFF_AL A_TILE_B                 // 18432
#define OFF_BH (2*A_TILE_B)             // 36864
#define OFF_BL (2*A_TILE_B + B_TILE_B)  // 73728
#define STAGE_B (2*A_TILE_B + 2*B_TILE_B) // 110592
#define GEMM_SMEM (2*STAGE_B)           // 221184

template<int MODE>
__global__ __launch_bounds__(512, 1)
void gemm_tc(const float* __restrict__ bias, float* __restrict__ Cout,
             int M, int Nn)
{
    const __nv_bfloat16* __restrict__ Ah = (MODE == 0) ? s_xh  : s_oh;
    const __nv_bfloat16* __restrict__ Al = (MODE == 0) ? s_xl  : s_ol;
    const __nv_bfloat16* __restrict__ Bh = (MODE == 0) ? s_qwh : s_pwh;
    const __nv_bfloat16* __restrict__ Bl = (MODE == 0) ? s_qwl : s_pwl;

    extern __shared__ char smem[];
    const uint32_t sb = (uint32_t)__cvta_generic_to_shared(smem);

    const int tid  = threadIdx.x;
    const int bm0  = blockIdx.y * GBM;
    const int bn0  = blockIdx.x * GBN;
    const int w    = tid >> 5;
    const int lane = tid & 31;
    const int wM   = w & 3;         // 4 strips of 32 rows
    const int wN   = w >> 2;        // 4 strips of 64 cols

    // zero A-tiles only when this block has an M-tail
    if (bm0 + GBM > M) {
        #pragma unroll
        for (int s = 0; s < 2; ++s)
            for (int i = tid; i < (2 * A_TILE_B) / 16; i += 512)
                ((uint4*)(smem + s * STAGE_B))[i] = make_uint4(0, 0, 0, 0);
    }
    __syncthreads();

    float acc[2][8][4];
    #pragma unroll
    for (int mt = 0; mt < 2; ++mt)
        #pragma unroll
        for (int nt = 0; nt < 8; ++nt)
            #pragma unroll
            for (int e = 0; e < 4; ++e) acc[mt][nt][e] = 0.f;

    // loader: A tiles 1024 chunks each (2/thread), B tiles 2048 (4/thread)
    auto load_stage = [&](int stage, int kt) {
        const int k0 = kt * GBKT;
        const uint32_t base = sb + stage * STAGE_B;
        #pragma unroll
        for (int i = 0; i < 2; ++i) {
            const int chunk = tid + (i << 9);
            const int r = chunk >> 3, c = chunk & 7;
            const uint32_t d = (uint32_t)(r * GPCH + c * 16);
            const int gm = bm0 + r;
            if (gm < M) {
                const size_t ao = (size_t)gm * KDIM + k0 + c * 8;
                cp16(base + OFF_AH + d, Ah + ao);
                cp16(base + OFF_AL + d, Al + ao);
            }
        }
        #pragma unroll
        for (int i = 0; i < 4; ++i) {
            const int chunk = tid + (i << 9);
            const int r = chunk >> 3, c = chunk & 7;
            const uint32_t d = (uint32_t)(r * GPCH + c * 16);
            const size_t bo = (size_t)(bn0 + r) * KDIM + k0 + c * 8;
            cp16(base + OFF_BH + d, Bh + bo);
            cp16(base + OFF_BL + d, Bl + bo);
        }
    };

    const int aRow = wM * 32 + (lane & 15);
    const int bRow = wN * 64 + (lane & 15);
    const int cSel = lane >> 4;

    const int NK = KDIM / GBKT;     // 12
    load_stage(0, 0);
    cp_commit();

    for (int kt = 0; kt < NK; ++kt) {
        cp_wait<0>();
        __syncthreads();
        if (kt + 1 < NK) {
            load_stage((kt + 1) & 1, kt + 1);
            cp_commit();
        }

        const uint32_t base = sb + (kt & 1) * STAGE_B;
        #pragma unroll
        for (int kk = 0; kk < 4; ++kk) {
            const int kb = kk * 2;
            uint32_t ah[2][4], al[2][4], bh[8][2], bl[8][2];
            #pragma unroll
            for (int mt = 0; mt < 2; ++mt) {
                const uint32_t ra = (aRow + mt * 16) * GPCH + (kb + cSel) * 16;
                ldsm4(ah[mt][0], ah[mt][1], ah[mt][2], ah[mt][3], base + OFF_AH + ra);
                ldsm4(al[mt][0], al[mt][1], al[mt][2], al[mt][3], base + OFF_AL + ra);
            }
            #pragma unroll
            for (int p = 0; p < 4; ++p) {
                const uint32_t rb = (bRow + p * 16) * GPCH + (kb + cSel) * 16;
                uint32_t t0, t1, t2, t3;
                ldsm4(t0, t1, t2, t3, base + OFF_BH + rb);
                bh[2*p][0] = t0; bh[2*p+1][0] = t1; bh[2*p][1] = t2; bh[2*p+1][1] = t3;
                ldsm4(t0, t1, t2, t3, base + OFF_BL + rb);
                bl[2*p][0] = t0; bl[2*p+1][0] = t1; bl[2*p][1] = t2; bl[2*p+1][1] = t3;
            }
            // product-major: hh then hl then lh (same per-acc order as R8)
            #pragma unroll
            for (int mt = 0; mt < 2; ++mt)
                #pragma unroll
                for (int nt = 0; nt < 8; ++nt) {
                    float* c = acc[mt][nt];
                    mma16816(c[0], c[1], c[2], c[3],
                             ah[mt][0], ah[mt][1], ah[mt][2], ah[mt][3],
                             bh[nt][0], bh[nt][1]);
                }
            #pragma unroll
            for (int mt = 0; mt < 2; ++mt)
                #pragma unroll
                for (int nt = 0; nt < 8; ++nt) {
                    float* c = acc[mt][nt];
                    mma16816(c[0], c[1], c[2], c[3],
                             ah[mt][0], ah[mt][1], ah[mt][2], ah[mt][3],
                             bl[nt][0], bl[nt][1]);
                }
            #pragma unroll
            for (int mt = 0; mt < 2; ++mt)
                #pragma unroll
                for (int nt = 0; nt < 8; ++nt) {
                    float* c = acc[mt][nt];
                    mma16816(c[0], c[1], c[2], c[3],
                             al[mt][0], al[mt][1], al[mt][2], al[mt][3],
                             bh[nt][0], bh[nt][1]);
                }
        }
    }

    const int mBase = bm0 + wM * 32 + (lane >> 2);
    const int nBase = bn0 + wN * 64 + ((lane & 3) << 1);
    #pragma unroll
    for (int mt = 0; mt < 2; ++mt) {
        #pragma unroll
        for (int half = 0; half < 2; ++half) {
            const int m = mBase + mt * 16 + half * 8;
            if (m >= M) continue;
            #pragma unroll
            for (int nt = 0; nt < 8; ++nt) {
                const int n = nBase + nt * 8;
                const float v0 = acc[mt][nt][half*2+0] + bias[n];
                const float v1 = acc[mt][nt][half*2+1] + bias[n+1];
                if (MODE == 0) {
                    const int b = m / SEQ;
                    const int t = m - b * SEQ;
                    #pragma unroll
                    for (int e = 0; e < 2; ++e) {
                        const int nn = n + e;
                        const float vv = e ? v1 : v0;
                        const int sel = nn / BC;
                        const int rr  = nn - sel * BC;
                        const int hh  = rr >> 6;
                        const int dd  = rr & 63;
                        float* dst = (sel == 0) ? g_q : (sel == 1) ? g_k : g_v;
                        dst[(((b * NH + hh) * SEQ + t) << 6) + dd] = vv;
                    }
                } else {
                    Cout[(size_t)m * Nn + n]     = v0;
                    Cout[(size_t)m * Nn + n + 1] = v1;
                }
            }
        }
    }
}

// ---------------------------------------------------------------------------
// Tensor-core attention (round-11 version: 13 warps, pipelined j-loop)
// ---------------------------------------------------------------------------
#define SEQP 208
#define AQ_PITCH 72
#define AV_PITCH 216
#define QH_OFF 0u
#define QL_OFF 29952u
#define KH_OFF 59904u
#define KL_OFF 89856u
#define VTH_OFF 119808u
#define VTL_OFF 147456u
#define ATTN_SMEM 175104
#define ATTN_THREADS 416

__global__ __launch_bounds__(ATTN_THREADS)
void attn_tc()
{
    extern __shared__ char asmem[];
    __nv_bfloat16* sb16 = (__nv_bfloat16*)asmem;
    const uint32_t sb = (uint32_t)__cvta_generic_to_shared(asmem);

    const int bh = blockIdx.x;
    const int b  = bh / NH;
    const int h  = bh - b * NH;
    const float* __restrict__ Qg = g_q + (size_t)bh * SEQ * HD;
    const float* __restrict__ Kg = g_k + (size_t)bh * SEQ * HD;
    const float* __restrict__ Vg = g_v + (size_t)bh * SEQ * HD;

    const int tid = threadIdx.x;

    for (int i = tid; i < 11 * HD; i += ATTN_THREADS) {
        const int t = SEQ + (i >> 6), d = i & 63;
        sb16[QH_OFF/2 + t*AQ_PITCH + d] = __nv_bfloat16(0.f);
        sb16[QL_OFF/2 + t*AQ_PITCH + d] = __nv_bfloat16(0.f);
        sb16[KH_OFF/2 + t*AQ_PITCH + d] = __nv_bfloat16(0.f);
        sb16[KL_OFF/2 + t*AQ_PITCH + d] = __nv_bfloat16(0.f);
    }
    for (int i = tid; i < HD * (AV_PITCH - SEQ); i += ATTN_THREADS) {
        const int d = i / (AV_PITCH - SEQ), t = SEQ + i % (AV_PITCH - SEQ);
        sb16[VTH_OFF/2 + d*AV_PITCH + t] = __nv_bfloat16(0.f);
        sb16[VTL_OFF/2 + d*AV_PITCH + t] = __nv_bfloat16(0.f);
    }
    __syncthreads();

    for (int i = tid; i < SEQ * HD; i += ATTN_THREADS) {
        const int t = i >> 6, d = i & 63;
        float q = Qg[i] * 0.125f;
        __nv_bfloat16 qh = __float2bfloat16_rn(q);
        sb16[QH_OFF/2 + t*AQ_PITCH + d] = qh;
        sb16[QL_OFF/2 + t*AQ_PITCH + d] = __float2bfloat16_rn(q - __bfloat162float(qh));
        float k = Kg[i];
        __nv_bfloat16 kh = __float2bfloat16_rn(k);
        sb16[KH_OFF/2 + t*AQ_PITCH + d] = kh;
        sb16[KL_OFF/2 + t*AQ_PITCH + d] = __float2bfloat16_rn(k - __bfloat162float(kh));
        float v = Vg[i];
        __nv_bfloat16 vh = __float2bfloat16_rn(v);
        sb16[VTH_OFF/2 + d*AV_PITCH + t] = vh;
        sb16[VTL_OFF/2 + d*AV_PITCH + t] = __float2bfloat16_rn(v - __bfloat162float(vh));
    }
    __syncthreads();

    const int w    = tid >> 5;
    const int lane = tid & 31;
    const int l15  = lane & 15;
    const int lhi  = lane >> 4;
    const int c2   = (lane & 3) << 1;
    const int r    = lane >> 2;

    const int m0 = w << 4;

    uint32_t aqh[4][4], aql[4][4];
    #pragma unroll
    for (int ks = 0; ks < 4; ++ks) {
        const uint32_t qa = sb + QH_OFF + (uint32_t)(m0 + l15) * 144u
                          + (uint32_t)((ks << 1) + lhi) * 16u;
        ldsm4(aqh[ks][0], aqh[ks][1], aqh[ks][2], aqh[ks][3], qa);
        ldsm4(aql[ks][0], aql[ks][1], aql[ks][2], aql[ks][3], qa + (QL_OFF - QH_OFF));
    }

    auto qk_tile = [&](int j, float* s) {
        #pragma unroll
        for (int e = 0; e < 8; ++e) s[e] = 0.f;
        #pragma unroll
        for (int ks = 0; ks < 4; ++ks) {
            const uint32_t ka = sb + KH_OFF + (uint32_t)((j << 4) + l15) * 144u
                              + (uint32_t)((ks << 1) + lhi) * 16u;
            uint32_t kh0,kh1,kh2,kh3, kl0,kl1,kl2,kl3;
            ldsm4(kh0,kh1,kh2,kh3, ka);
            ldsm4(kl0,kl1,kl2,kl3, ka + (KL_OFF - KH_OFF));
            mma16816(s[0],s[1],s[2],s[3],
                     aqh[ks][0],aqh[ks][1],aqh[ks][2],aqh[ks][3], kh0, kh2);
            mma16816(s[4],s[5],s[6],s[7],
                     aqh[ks][0],aqh[ks][1],aqh[ks][2],aqh[ks][3], kh1, kh3);
            mma16816(s[0],s[1],s[2],s[3],
                     aqh[ks][0],aqh[ks][1],aqh[ks][2],aqh[ks][3], kl0, kl2);
            mma16816(s[4],s[5],s[6],s[7],
                     aqh[ks][0],aqh[ks][1],aqh[ks][2],aqh[ks][3], kl1, kl3);
            mma16816(s[0],s[1],s[2],s[3],
                     aql[ks][0],aql[ks][1],aql[ks][2],aql[ks][3], kh0, kh2);
            mma16816(s[4],s[5],s[6],s[7],
                     aql[ks][0],aql[ks][1],aql[ks][2],aql[ks][3], kh1, kh3);
        }
    };

    float o[8][4];
    #pragma unroll
    for (int t = 0; t < 8; ++t)
        #pragma unroll
        for (int e = 0; e < 4; ++e) o[t][e] = 0.f;
    float ls0 = 0.f, ls1 = 0.f;

    float scur[8];
    qk_tile(0, scur);

    for (int j = 0; j < 13; ++j) {
        float snxt[8];
        if (j < 12) qk_tile(j + 1, snxt);

        const int kb = (j << 4) + c2;
        const bool v0 = (kb     < SEQ), v1 = (kb + 1 < SEQ);
        const bool v8 = (kb + 8 < SEQ), v9 = (kb + 9 < SEQ);
        const float p00 = v0 ? __expf(scur[0]) : 0.f;
        const float p01 = v1 ? __expf(scur[1]) : 0.f;
        const float p02 = v0 ? __expf(scur[2]) : 0.f;
        const float p03 = v1 ? __expf(scur[3]) : 0.f;
        const float p10 = v8 ? __expf(scur[4]) : 0.f;
        const float p11 = v9 ? __expf(scur[5]) : 0.f;
        const float p12 = v8 ? __expf(scur[6]) : 0.f;
        const float p13 = v9 ? __expf(scur[7]) : 0.f;
        ls0 += (p00 + p01) + (p10 + p11);
        ls1 += (p02 + p03) + (p12 + p13);

        const float h00 = __bfloat162float(__float2bfloat16_rn(p00));
        const float h01 = __bfloat162float(__float2bfloat16_rn(p01));
        const float h02 = __bfloat162float(__float2bfloat16_rn(p02));
        const float h03 = __bfloat162float(__float2bfloat16_rn(p03));
        const float h10 = __bfloat162float(__float2bfloat16_rn(p10));
        const float h11 = __bfloat162float(__float2bfloat16_rn(p11));
        const float h12 = __bfloat162float(__float2bfloat16_rn(p12));
        const float h13 = __bfloat162float(__float2bfloat16_rn(p13));
        uint32_t pah[4], pal[4];
        pah[0] = pack_bf2(h00, h01); pal[0] = pack_bf2(p00 - h00, p01 - h01);
        pah[1] = pack_bf2(h02, h03); pal[1] = pack_bf2(p02 - h02, p03 - h03);
        pah[2] = pack_bf2(h10, h11); pal[2] = pack_bf2(p10 - h10, p11 - h11);
        pah[3] = pack_bf2(h12, h13); pal[3] = pack_bf2(p12 - h12, p13 - h13);

        #pragma unroll
        for (int g = 0; g < 4; ++g) {
            const uint32_t va = sb + VTH_OFF + (uint32_t)((g << 4) + l15) * 432u
                              + (uint32_t)((j << 1) + lhi) * 16u;
            uint32_t vh0,vh1,vh2,vh3, vl0,vl1,vl2,vl3;
            ldsm4(vh0,vh1,vh2,vh3, va);
            ldsm4(vl0,vl1,vl2,vl3, va + (VTL_OFF - VTH_OFF));
            float* oa = o[g*2];
            float* ob = o[g*2+1];
            mma16816(oa[0],oa[1],oa[2],oa[3], pah[0],pah[1],pah[2],pah[3], vh0, vh2);
            mma16816(ob[0],ob[1],ob[2],ob[3], pah[0],pah[1],pah[2],pah[3], vh1, vh3);
            mma16816(oa[0],oa[1],oa[2],oa[3], pah[0],pah[1],pah[2],pah[3], vl0, vl2);
            mma16816(ob[0],ob[1],ob[2],ob[3], pah[0],pah[1],pah[2],pah[3], vl1, vl3);
            mma16816(oa[0],oa[1],oa[2],oa[3], pal[0],pal[1],pal[2],pal[3], vh0, vh2);
            mma16816(ob[0],ob[1],ob[2],ob[3], pal[0],pal[1],pal[2],pal[3], vh1, vh3);
        }

        #pragma unroll
        for (int e = 0; e < 8; ++e) scur[e] = snxt[e];
    }

    ls0 += __shfl_xor_sync(0xffffffffu, ls0, 1);
    ls0 += __shfl_xor_sync(0xffffffffu, ls0, 2);
    ls1 += __shfl_xor_sync(0xffffffffu, ls1, 1);
    ls1 += __shfl_xor_sync(0xffffffffu, ls1, 2);
    const float inv0 = 1.f / ls0;
    const float inv1 = 1.f / ls1;

    const int row0 = m0 + r;
    const int row1 = row0 + 8;
    #pragma unroll
    for (int t = 0; t < 8; ++t) {
        const int d = h * HD + t * 8 + c2;
        if (row0 < SEQ) {
            const size_t base = (size_t)(b * SEQ + row0) * BC + d;
            const float y0 = o[t][0] * inv0, y1 = o[t][1] * inv0;
            const __nv_bfloat16 yh0 = __float2bfloat16_rn(y0);
            const __nv_bfloat16 yh1 = __float2bfloat16_rn(y1);
            s_oh[base]   = yh0;
            s_oh[base+1] = yh1;
            s_ol[base]   = __float2bfloat16_rn(y0 - __bfloat162float(yh0));
            s_ol[base+1] = __float2bfloat16_rn(y1 - __bfloat162float(yh1));
        }
        if (row1 < SEQ) {
            const size_t base = (size_t)(b * SEQ + row1) * BC + d;
            const float y0 = o[t][2] * inv1, y1 = o[t][3] * inv1;
            const __nv_bfloat16 yh0 = __float2bfloat16_rn(y0);
            const __nv_bfloat16 yh1 = __float2bfloat16_rn(y1);
            s_oh[base]   = yh0;
            s_oh[base+1] = yh1;
            s_ol[base]   = __float2bfloat16_rn(y0 - __bfloat162float(yh0));
            s_ol[base+1] = __float2bfloat16_rn(y1 - __bfloat162float(yh1));
        }
    }
}

// ---------------------------------------------------------------------------
extern "C" void kernel_launch(void* const* d_in, const int* in_sizes, int n_in,
                              void* d_out, int out_size)
{
    const float* x  = (const float*)d_in[0];
    const float* qw = (const float*)d_in[1];
    const float* qb = (const float*)d_in[2];
    const float* pw = (const float*)d_in[3];
    const float* pb = (const float*)d_in[4];
    float* out = (float*)d_out;

    // smoothquant power-of-2 channel scaling cancels bit-exactly in fp32: skipped.

    cudaFuncSetAttribute(attn_tc,
                         cudaFuncAttributeMaxDynamicSharedMemorySize, ATTN_SMEM);
    cudaFuncSetAttribute(gemm_tc<0>,
                         cudaFuncAttributeMaxDynamicSharedMemorySize, GEMM_SMEM);
    cudaFuncSetAttribute(gemm_tc<1>,
                         cudaFuncAttributeMaxDynamicSharedMemorySize, GEMM_SMEM);

    { int n4 = M_TOT*BC/4;  split_kernel<0><<<(n4+255)/256,256>>>((const float4*)x,  n4); }
    { int n4 = QKV_N*BC/4;  split_kernel<1><<<(n4+255)/256,256>>>((const float4*)qw, n4); }
    { int n4 = BC*BC/4;     split_kernel<2><<<(n4+255)/256,256>>>((const float4*)pw, n4); }

    dim3 g1(QKV_N / GBN, (M_TOT + GBM - 1) / GBM);   // 9 x 99
    gemm_tc<0><<<g1, 512, GEMM_SMEM>>>(qb, nullptr, M_TOT, QKV_N);

    attn_tc<<<BATCH * NH, ATTN_THREADS, ATTN_SMEM>>>();

    dim3 g2(BC / GBN, (M_TOT + GBM - 1) / GBM);      // 3 x 99
    gemm_tc<1><<<g2, 512, GEMM_SMEM>>>(pb, out, M_TOT, BC);
}

// round 13
// speedup vs baseline: 1.0500x; 1.0500x over previous
#include <cuda_runtime.h>
#include <cuda_bf16.h>
#include <cstdint>

// Problem constants
#define BC    768
#define NH    12
#define HD    64
#define SEQ   197
#define BATCH 64
#define M_TOT (BATCH*SEQ)     // 12608
#define QKV_N (3*BC)          // 2304
#define KDIM  768

// ---------------- scratch (static __device__, allocation-free) -------------
__device__ float g_q[BATCH*NH*SEQ*HD];
__device__ float g_k[BATCH*NH*SEQ*HD];
__device__ float g_v[BATCH*NH*SEQ*HD];

__device__ __nv_bfloat16 s_xh[M_TOT*BC],  s_xl[M_TOT*BC];
__device__ __nv_bfloat16 s_qwh[QKV_N*BC], s_qwl[QKV_N*BC];
__device__ __nv_bfloat16 s_pwh[BC*BC],    s_pwl[BC*BC];
__device__ __nv_bfloat16 s_oh[M_TOT*BC],  s_ol[M_TOT*BC];

// ---------------------------------------------------------------------------
// Fused fp32 -> (hi,lo) bf16 split for all three tensors in ONE launch.
// Segment 0: x -> s_x*, segment 1: qkv_weight -> s_qw*, segment 2: proj_weight.
// Per-element math identical to the previous per-tensor kernels.
// ---------------------------------------------------------------------------
#define N4_X  (M_TOT*BC/4)     // 2420736
#define N4_QW (QKV_N*BC/4)     // 442368
#define N4_PW (BC*BC/4)        // 147456
#define N4_ALL (N4_X + N4_QW + N4_PW)

__global__ void split_all(const float4* __restrict__ x,
                          const float4* __restrict__ qw,
                          const float4* __restrict__ pw)
{
    int idx = blockIdx.x * blockDim.x + threadIdx.x;
    if (idx >= N4_ALL) return;

    const float4* src;
    __nv_bfloat16 *hi, *lo;
    int i;
    if (idx < N4_X)               { src = x;  hi = s_xh;  lo = s_xl;  i = idx; }
    else if (idx < N4_X + N4_QW)  { src = qw; hi = s_qwh; lo = s_qwl; i = idx - N4_X; }
    else                          { src = pw; hi = s_pwh; lo = s_pwl; i = idx - N4_X - N4_QW; }

    float4 v = src[i];
    float f[4] = {v.x, v.y, v.z, v.w};
    __nv_bfloat16 h[4], l[4];
    #pragma unroll
    for (int j = 0; j < 4; ++j) {
        h[j] = __float2bfloat16_rn(f[j]);
        l[j] = __float2bfloat16_rn(f[j] - __bfloat162float(h[j]));
    }
    __nv_bfloat162* hp = (__nv_bfloat162*)hi;
    __nv_bfloat162* lp = (__nv_bfloat162*)lo;
    hp[i*2+0] = __nv_bfloat162(h[0], h[1]);
    hp[i*2+1] = __nv_bfloat162(h[2], h[3]);
    lp[i*2+0] = __nv_bfloat162(l[0], l[1]);
    lp[i*2+1] = __nv_bfloat162(l[2], l[3]);
}

// ---------------------------------------------------------------------------
// PTX helpers
// ---------------------------------------------------------------------------
__device__ __forceinline__ void ldsm4(uint32_t& r0, uint32_t& r1,
                                      uint32_t& r2, uint32_t& r3, uint32_t a)
{
    asm volatile("ldmatrix.sync.aligned.m8n8.x4.shared.b16 {%0,%1,%2,%3},[%4];"
                 : "=r"(r0), "=r"(r1), "=r"(r2), "=r"(r3) : "r"(a));
}
__device__ __forceinline__ void mma16816(float& c0, float& c1, float& c2, float& c3,
                                         uint32_t a0, uint32_t a1, uint32_t a2, uint32_t a3,
                                         uint32_t b0, uint32_t b1)
{
    asm volatile("mma.sync.aligned.m16n8k16.row.col.f32.bf16.bf16.f32 "
                 "{%0,%1,%2,%3},{%4,%5,%6,%7},{%8,%9},{%0,%1,%2,%3};"
                 : "+f"(c0), "+f"(c1), "+f"(c2), "+f"(c3)
                 : "r"(a0), "r"(a1), "r"(a2), "r"(a3), "r"(b0), "r"(b1));
}
__device__ __forceinline__ void cp16(uint32_t d, const void* s)
{
    asm volatile("cp.async.cg.shared.global [%0],[%1],16;" :: "r"(d), "l"(s));
}
__device__ __forceinline__ void cp_commit() { asm volatile("cp.async.commit_group;"); }
template<int N>
__device__ __forceinline__ void cp_wait() { asm volatile("cp.async.wait_group %0;" :: "n"(N)); }

__device__ __forceinline__ uint32_t pack_bf2(float x, float y)
{
    __nv_bfloat162 t(__float2bfloat16_rn(x), __float2bfloat16_rn(y));
    return *(uint32_t*)&t;
}

// ---------------------------------------------------------------------------
// bf16x3 tensor-core GEMM — round-8/11 champion configuration (490us floor).
// MODE 0: A=s_x*, B=s_qw*, scatter -> g_q/g_k/g_v    MODE 1: A=s_o*, B=s_pw*
// ---------------------------------------------------------------------------
#define BM 128
#define BN 128
#define BKT 32
#define PCHB 80
#define TILE_B (128*PCHB)
#define STAGE_B (4*TILE_B)
#define OFF_AH 0
#define OFF_AL TILE_B
#define OFF_BH (2*TILE_B)
#define OFF_BL (3*TILE_B)
#define GEMM_SMEM (2*STAGE_B)

template<int MODE>
__global__ __launch_bounds__(256, 2)
void gemm_tc(const float* __restrict__ bias, float* __restrict__ Cout,
             int M, int Nn)
{
    const __nv_bfloat16* __restrict__ Ah = (MODE == 0) ? s_xh  : s_oh;
    const __nv_bfloat16* __restrict__ Al = (MODE == 0) ? s_xl  : s_ol;
    const __nv_bfloat16* __restrict__ Bh = (MODE == 0) ? s_qwh : s_pwh;
    const __nv_bfloat16* __restrict__ Bl = (MODE == 0) ? s_qwl : s_pwl;

    extern __shared__ char smem[];
    const uint32_t sb = (uint32_t)__cvta_generic_to_shared(smem);

    const int tid  = threadIdx.x;
    const int bm0  = blockIdx.y * BM;
    const int bn0  = blockIdx.x * BN;
    const int w    = tid >> 5;
    const int lane = tid & 31;
    const int wM   = w >> 1;
    const int wN   = w & 1;

    for (int i = tid; i < GEMM_SMEM / 16; i += 256)
        ((uint4*)smem)[i] = make_uint4(0, 0, 0, 0);
    __syncthreads();

    const int c0row = tid >> 2, c0kc = tid & 3;
    const int c1row = (tid + 256) >> 2, c1kc = tid & 3;

    float acc[2][8][4];
    #pragma unroll
    for (int mt = 0; mt < 2; ++mt)
        #pragma unroll
        for (int nt = 0; nt < 8; ++nt)
            #pragma unroll
            for (int e = 0; e < 4; ++e) acc[mt][nt][e] = 0.f;

    auto load_stage = [&](int stage, int kt) {
        const int k0 = kt * BKT;
        const uint32_t base = sb + stage * STAGE_B;
        #pragma unroll
        for (int h = 0; h < 2; ++h) {
            const int row = h ? c1row : c0row;
            const int kc  = h ? c1kc  : c0kc;
            const uint32_t doff = row * PCHB + kc * 16;
            const int gcol = k0 + kc * 8;
            const int gm = bm0 + row;
            if (gm < M) {
                const size_t ao = (size_t)gm * KDIM + gcol;
                cp16(base + OFF_AH + doff, Ah + ao);
                cp16(base + OFF_AL + doff, Al + ao);
            }
            const size_t bo = (size_t)(bn0 + row) * KDIM + gcol;
            cp16(base + OFF_BH + doff, Bh + bo);
            cp16(base + OFF_BL + doff, Bl + bo);
        }
    };

    const int aRow  = wM * 32 + (lane & 15);
    const int bRow  = wN * 64 + (lane & 15);
    const int cSel  = lane >> 4;

    const int NK = KDIM / BKT;
    load_stage(0, 0);
    cp_commit();

    for (int kt = 0; kt < NK; ++kt) {
        cp_wait<0>();
        __syncthreads();
        if (kt + 1 < NK) {
            load_stage((kt + 1) & 1, kt + 1);
            cp_commit();
        }

        const uint32_t base = sb + (kt & 1) * STAGE_B;
        #pragma unroll
        for (int kk = 0; kk < 2; ++kk) {
            const int kb = kk * 2;
            uint32_t ah[2][4], al[2][4], bh[8][2], bl[8][2];
            #pragma unroll
            for (int mt = 0; mt < 2; ++mt) {
                const uint32_t ra = (aRow + mt * 16) * PCHB + (kb + cSel) * 16;
                ldsm4(ah[mt][0], ah[mt][1], ah[mt][2], ah[mt][3], base + OFF_AH + ra);
                ldsm4(al[mt][0], al[mt][1], al[mt][2], al[mt][3], base + OFF_AL + ra);
            }
            #pragma unroll
            for (int p = 0; p < 4; ++p) {
                const uint32_t rb = (bRow + p * 16) * PCHB + (kb + cSel) * 16;
                uint32_t t0, t1, t2, t3;
                ldsm4(t0, t1, t2, t3, base + OFF_BH + rb);
                bh[2*p][0] = t0; bh[2*p+1][0] = t1; bh[2*p][1] = t2; bh[2*p+1][1] = t3;
                ldsm4(t0, t1, t2, t3, base + OFF_BL + rb);
                bl[2*p][0] = t0; bl[2*p+1][0] = t1; bl[2*p][1] = t2; bl[2*p+1][1] = t3;
            }
            #pragma unroll
            for (int mt = 0; mt < 2; ++mt)
                #pragma unroll
                for (int nt = 0; nt < 8; ++nt) {
                    float* c = acc[mt][nt];
                    mma16816(c[0], c[1], c[2], c[3],
                             ah[mt][0], ah[mt][1], ah[mt][2], ah[mt][3],
                             bh[nt][0], bh[nt][1]);
                }
            #pragma unroll
            for (int mt = 0; mt < 2; ++mt)
                #pragma unroll
                for (int nt = 0; nt < 8; ++nt) {
                    float* c = acc[mt][nt];
                    mma16816(c[0], c[1], c[2], c[3],
                             ah[mt][0], ah[mt][1], ah[mt][2], ah[mt][3],
                             bl[nt][0], bl[nt][1]);
                }
            #pragma unroll
            for (int mt = 0; mt < 2; ++mt)
                #pragma unroll
                for (int nt = 0; nt < 8; ++nt) {
                    float* c = acc[mt][nt];
                    mma16816(c[0], c[1], c[2], c[3],
                             al[mt][0], al[mt][1], al[mt][2], al[mt][3],
                             bh[nt][0], bh[nt][1]);
                }
        }
    }

    const int mBase = bm0 + wM * 32 + (lane >> 2);
    const int nBase = bn0 + wN * 64 + ((lane & 3) << 1);
    #pragma unroll
    for (int mt = 0; mt < 2; ++mt) {
        #pragma unroll
        for (int half = 0; half < 2; ++half) {
            const int m = mBase + mt * 16 + half * 8;
            if (m >= M) continue;
            #pragma unroll
            for (int nt = 0; nt < 8; ++nt) {
                const int n = nBase + nt * 8;
                const float v0 = acc[mt][nt][half*2+0] + bias[n];
                const float v1 = acc[mt][nt][half*2+1] + bias[n+1];
                if (MODE == 0) {
                    const int b = m / SEQ;
                    const int t = m - b * SEQ;
                    #pragma unroll
                    for (int e = 0; e < 2; ++e) {
                        const int nn = n + e;
                        const float vv = e ? v1 : v0;
                        const int sel = nn / BC;
                        const int rr  = nn - sel * BC;
                        const int hh  = rr >> 6;
                        const int dd  = rr & 63;
                        float* dst = (sel == 0) ? g_q : (sel == 1) ? g_k : g_v;
                        dst[(((b * NH + hh) * SEQ + t) << 6) + dd] = vv;
                    }
                } else {
                    Cout[(size_t)m * Nn + n]     = v0;
                    Cout[(size_t)m * Nn + n + 1] = v1;
                }
            }
        }
    }
}

// ---------------------------------------------------------------------------
// Tensor-core attention (round-11 champion: 13 warps, pipelined j-loop).
// Change vs R11: fill loop uses float4 global reads (4 consecutive d per
// thread) -> 4x fewer LDGs in the load phase. Same math, same stores.
// ---------------------------------------------------------------------------
#define SEQP 208
#define AQ_PITCH 72
#define AV_PITCH 216
#define QH_OFF 0u
#define QL_OFF 29952u
#define KH_OFF 59904u
#define KL_OFF 89856u
#define VTH_OFF 119808u
#define VTL_OFF 147456u
#define ATTN_SMEM 175104
#define ATTN_THREADS 416

__global__ __launch_bounds__(ATTN_THREADS)
void attn_tc()
{
    extern __shared__ char asmem[];
    __nv_bfloat16* sb16 = (__nv_bfloat16*)asmem;
    const uint32_t sb = (uint32_t)__cvta_generic_to_shared(asmem);

    const int bh = blockIdx.x;
    const int b  = bh / NH;
    const int h  = bh - b * NH;
    const float* __restrict__ Qg = g_q + (size_t)bh * SEQ * HD;
    const float* __restrict__ Kg = g_k + (size_t)bh * SEQ * HD;
    const float* __restrict__ Vg = g_v + (size_t)bh * SEQ * HD;

    const int tid = threadIdx.x;

    // zero only padding (rows 197..207 of Q/K; cols 197..215 of V^T)
    for (int i = tid; i < 11 * HD; i += ATTN_THREADS) {
        const int t = SEQ + (i >> 6), d = i & 63;
        sb16[QH_OFF/2 + t*AQ_PITCH + d] = __nv_bfloat16(0.f);
        sb16[QL_OFF/2 + t*AQ_PITCH + d] = __nv_bfloat16(0.f);
        sb16[KH_OFF/2 + t*AQ_PITCH + d] = __nv_bfloat16(0.f);
        sb16[KL_OFF/2 + t*AQ_PITCH + d] = __nv_bfloat16(0.f);
    }
    for (int i = tid; i < HD * (AV_PITCH - SEQ); i += ATTN_THREADS) {
        const int d = i / (AV_PITCH - SEQ), t = SEQ + i % (AV_PITCH - SEQ);
        sb16[VTH_OFF/2 + d*AV_PITCH + t] = __nv_bfloat16(0.f);
        sb16[VTL_OFF/2 + d*AV_PITCH + t] = __nv_bfloat16(0.f);
    }
    __syncthreads();

    // fill: float4 loads, 4 consecutive d per thread
    const float4* __restrict__ Qg4 = (const float4*)Qg;
    const float4* __restrict__ Kg4 = (const float4*)Kg;
    const float4* __restrict__ Vg4 = (const float4*)Vg;
    for (int i = tid; i < SEQ * HD / 4; i += ATTN_THREADS) {
        const int t = i >> 4;              // (i*4) >> 6
        const int d0 = (i << 2) & 63;
        const float4 qv4 = Qg4[i];
        const float4 kv4 = Kg4[i];
        const float4 vv4 = Vg4[i];
        const float qf[4] = {qv4.x, qv4.y, qv4.z, qv4.w};
        const float kf[4] = {kv4.x, kv4.y, kv4.z, kv4.w};
        const float vf[4] = {vv4.x, vv4.y, vv4.z, vv4.w};
        #pragma unroll
        for (int e = 0; e < 4; ++e) {
            const int d = d0 + e;
            const float q = qf[e] * 0.125f;
            const __nv_bfloat16 qh = __float2bfloat16_rn(q);
            sb16[QH_OFF/2 + t*AQ_PITCH + d] = qh;
            sb16[QL_OFF/2 + t*AQ_PITCH + d] = __float2bfloat16_rn(q - __bfloat162float(qh));
            const float k = kf[e];
            const __nv_bfloat16 kh = __float2bfloat16_rn(k);
            sb16[KH_OFF/2 + t*AQ_PITCH + d] = kh;
            sb16[KL_OFF/2 + t*AQ_PITCH + d] = __float2bfloat16_rn(k - __bfloat162float(kh));
            const float v = vf[e];
            const __nv_bfloat16 vh = __float2bfloat16_rn(v);
            sb16[VTH_OFF/2 + d*AV_PITCH + t] = vh;
            sb16[VTL_OFF/2 + d*AV_PITCH + t] = __float2bfloat16_rn(v - __bfloat162float(vh));
        }
    }
    __syncthreads();

    const int w    = tid >> 5;
    const int lane = tid & 31;
    const int l15  = lane & 15;
    const int lhi  = lane >> 4;
    const int c2   = (lane & 3) << 1;
    const int r    = lane >> 2;

    const int m0 = w << 4;

    uint32_t aqh[4][4], aql[4][4];
    #pragma unroll
    for (int ks = 0; ks < 4; ++ks) {
        const uint32_t qa = sb + QH_OFF + (uint32_t)(m0 + l15) * 144u
                          + (uint32_t)((ks << 1) + lhi) * 16u;
        ldsm4(aqh[ks][0], aqh[ks][1], aqh[ks][2], aqh[ks][3], qa);
        ldsm4(aql[ks][0], aql[ks][1], aql[ks][2], aql[ks][3], qa + (QL_OFF - QH_OFF));
    }

    auto qk_tile = [&](int j, float* s) {
        #pragma unroll
        for (int e = 0; e < 8; ++e) s[e] = 0.f;
        #pragma unroll
        for (int ks = 0; ks < 4; ++ks) {
            const uint32_t ka = sb + KH_OFF + (uint32_t)((j << 4) + l15) * 144u
                              + (uint32_t)((ks << 1) + lhi) * 16u;
            uint32_t kh0,kh1,kh2,kh3, kl0,kl1,kl2,kl3;
            ldsm4(kh0,kh1,kh2,kh3, ka);
            ldsm4(kl0,kl1,kl2,kl3, ka + (KL_OFF - KH_OFF));
            mma16816(s[0],s[1],s[2],s[3],
                     aqh[ks][0],aqh[ks][1],aqh[ks][2],aqh[ks][3], kh0, kh2);
            mma16816(s[4],s[5],s[6],s[7],
                     aqh[ks][0],aqh[ks][1],aqh[ks][2],aqh[ks][3], kh1, kh3);
            mma16816(s[0],s[1],s[2],s[3],
                     aqh[ks][0],aqh[ks][1],aqh[ks][2],aqh[ks][3], kl0, kl2);
            mma16816(s[4],s[5],s[6],s[7],
                     aqh[ks][0],aqh[ks][1],aqh[ks][2],aqh[ks][3], kl1, kl3);
            mma16816(s[0],s[1],s[2],s[3],
                     aql[ks][0],aql[ks][1],aql[ks][2],aql[ks][3], kh0, kh2);
            mma16816(s[4],s[5],s[6],s[7],
                     aql[ks][0],aql[ks][1],aql[ks][2],aql[ks][3], kh1, kh3);
        }
    };

    float o[8][4];
    #pragma unroll
    for (int t = 0; t < 8; ++t)
        #pragma unroll
        for (int e = 0; e < 4; ++e) o[t][e] = 0.f;
    float ls0 = 0.f, ls1 = 0.f;

    float scur[8];
    qk_tile(0, scur);

    for (int j = 0; j < 13; ++j) {
        float snxt[8];
        if (j < 12) qk_tile(j + 1, snxt);

        const int kb = (j << 4) + c2;
        const bool v0 = (kb     < SEQ), v1 = (kb + 1 < SEQ);
        const bool v8 = (kb + 8 < SEQ), v9 = (kb + 9 < SEQ);
        const float p00 = v0 ? __expf(scur[0]) : 0.f;
        const float p01 = v1 ? __expf(scur[1]) : 0.f;
        const float p02 = v0 ? __expf(scur[2]) : 0.f;
        const float p03 = v1 ? __expf(scur[3]) : 0.f;
        const float p10 = v8 ? __expf(scur[4]) : 0.f;
        const float p11 = v9 ? __expf(scur[5]) : 0.f;
        const float p12 = v8 ? __expf(scur[6]) : 0.f;
        const float p13 = v9 ? __expf(scur[7]) : 0.f;
        ls0 += (p00 + p01) + (p10 + p11);
        ls1 += (p02 + p03) + (p12 + p13);

        const float h00 = __bfloat162float(__float2bfloat16_rn(p00));
        const float h01 = __bfloat162float(__float2bfloat16_rn(p01));
        const float h02 = __bfloat162float(__float2bfloat16_rn(p02));
        const float h03 = __bfloat162float(__float2bfloat16_rn(p03));
        const float h10 = __bfloat162float(__float2bfloat16_rn(p10));
        const float h11 = __bfloat162float(__float2bfloat16_rn(p11));
        const float h12 = __bfloat162float(__float2bfloat16_rn(p12));
        const float h13 = __bfloat162float(__float2bfloat16_rn(p13));
        uint32_t pah[4], pal[4];
        pah[0] = pack_bf2(h00, h01); pal[0] = pack_bf2(p00 - h00, p01 - h01);
        pah[1] = pack_bf2(h02, h03); pal[1] = pack_bf2(p02 - h02, p03 - h03);
        pah[2] = pack_bf2(h10, h11); pal[2] = pack_bf2(p10 - h10, p11 - h11);
        pah[3] = pack_bf2(h12, h13); pal[3] = pack_bf2(p12 - h12, p13 - h13);

        #pragma unroll
        for (int g = 0; g < 4; ++g) {
            const uint32_t va = sb + VTH_OFF + (uint32_t)((g << 4) + l15) * 432u
                              + (uint32_t)((j << 1) + lhi) * 16u;
            uint32_t vh0,vh1,vh2,vh3, vl0,vl1,vl2,vl3;
            ldsm4(vh0,vh1,vh2,vh3, va);
            ldsm4(vl0,vl1,vl2,vl3, va + (VTL_OFF - VTH_OFF));
            float* oa = o[g*2];
            float* ob = o[g*2+1];
            mma16816(oa[0],oa[1],oa[2],oa[3], pah[0],pah[1],pah[2],pah[3], vh0, vh2);
            mma16816(ob[0],ob[1],ob[2],ob[3], pah[0],pah[1],pah[2],pah[3], vh1, vh3);
            mma16816(oa[0],oa[1],oa[2],oa[3], pah[0],pah[1],pah[2],pah[3], vl0, vl2);
            mma16816(ob[0],ob[1],ob[2],ob[3], pah[0],pah[1],pah[2],pah[3], vl1, vl3);
            mma16816(oa[0],oa[1],oa[2],oa[3], pal[0],pal[1],pal[2],pal[3], vh0, vh2);
            mma16816(ob[0],ob[1],ob[2],ob[3], pal[0],pal[1],pal[2],pal[3], vh1, vh3);
        }

        #pragma unroll
        for (int e = 0; e < 8; ++e) scur[e] = snxt[e];
    }

    ls0 += __shfl_xor_sync(0xffffffffu, ls0, 1);
    ls0 += __shfl_xor_sync(0xffffffffu, ls0, 2);
    ls1 += __shfl_xor_sync(0xffffffffu, ls1, 1);
    ls1 += __shfl_xor_sync(0xffffffffu, ls1, 2);
    const float inv0 = 1.f / ls0;
    const float inv1 = 1.f / ls1;

    const int row0 = m0 + r;
    const int row1 = row0 + 8;
    #pragma unroll
    for (int t = 0; t < 8; ++t) {
        const int d = h * HD + t * 8 + c2;
        if (row0 < SEQ) {
            const size_t base = (size_t)(b * SEQ + row0) * BC + d;
            const float y0 = o[t][0] * inv0, y1 = o[t][1] * inv0;
            const __nv_bfloat16 yh0 = __float2bfloat16_rn(y0);
            const __nv_bfloat16 yh1 = __float2bfloat16_rn(y1);
            s_oh[base]   = yh0;
            s_oh[base+1] = yh1;
            s_ol[base]   = __float2bfloat16_rn(y0 - __bfloat162float(yh0));
            s_ol[base+1] = __float2bfloat16_rn(y1 - __bfloat162float(yh1));
        }
        if (row1 < SEQ) {
            const size_t base = (size_t)(b * SEQ + row1) * BC + d;
            const float y0 = o[t][2] * inv1, y1 = o[t][3] * inv1;
            const __nv_bfloat16 yh0 = __float2bfloat16_rn(y0);
            const __nv_bfloat16 yh1 = __float2bfloat16_rn(y1);
            s_oh[base]   = yh0;
            s_oh[base+1] = yh1;
            s_ol[base]   = __float2bfloat16_rn(y0 - __bfloat162float(yh0));
            s_ol[base+1] = __float2bfloat16_rn(y1 - __bfloat162float(yh1));
        }
    }
}

// ---------------------------------------------------------------------------
extern "C" void kernel_launch(void* const* d_in, const int* in_sizes, int n_in,
                              void* d_out, int out_size)
{
    const float* x  = (const float*)d_in[0];
    const float* qw = (const float*)d_in[1];
    const float* qb = (const float*)d_in[2];
    const float* pw = (const float*)d_in[3];
    const float* pb = (const float*)d_in[4];
    float* out = (float*)d_out;

    // smoothquant power-of-2 channel scaling cancels bit-exactly in fp32: skipped.

    cudaFuncSetAttribute(attn_tc,
                         cudaFuncAttributeMaxDynamicSharedMemorySize, ATTN_SMEM);
    cudaFuncSetAttribute(gemm_tc<0>,
                         cudaFuncAttributeMaxDynamicSharedMemorySize, GEMM_SMEM);
    cudaFuncSetAttribute(gemm_tc<1>,
                         cudaFuncAttributeMaxDynamicSharedMemorySize, GEMM_SMEM);

    split_all<<<(N4_ALL + 255) / 256, 256>>>((const float4*)x, (const float4*)qw,
                                             (const float4*)pw);

    dim3 g1(QKV_N / BN, (M_TOT + BM - 1) / BM);   // 18 x 99
    gemm_tc<0><<<g1, 256, GEMM_SMEM>>>(qb, nullptr, M_TOT, QKV_N);

    attn_tc<<<BATCH * NH, ATTN_THREADS, ATTN_SMEM>>>();

    dim3 g2(BC / BN, (M_TOT + BM - 1) / BM);      // 6 x 99
    gemm_tc<1><<<g2, 256, GEMM_SMEM>>>(pb, out, M_TOT, BC);
}

// round 14
// speedup vs baseline: 1.0800x; 1.0286x over previous
#include <cuda_runtime.h>
#include <cuda_bf16.h>
#include <cstdint>

// Problem constants
#define BC    768
#define NH    12
#define HD    64
#define SEQ   197
#define BATCH 64
#define M_TOT (BATCH*SEQ)     // 12608 = 197 * 64 (exact!)
#define QKV_N (3*BC)          // 2304
#define KDIM  768

// ---------------- scratch (static __device__, allocation-free) -------------
__device__ float g_q[BATCH*NH*SEQ*HD];
__device__ float g_k[BATCH*NH*SEQ*HD];
__device__ float g_v[BATCH*NH*SEQ*HD];

__device__ __nv_bfloat16 s_xh[M_TOT*BC],  s_xl[M_TOT*BC];
__device__ __nv_bfloat16 s_qwh[QKV_N*BC], s_qwl[QKV_N*BC];
__device__ __nv_bfloat16 s_pwh[BC*BC],    s_pwl[BC*BC];
__device__ __nv_bfloat16 s_oh[M_TOT*BC],  s_ol[M_TOT*BC];

// ---------------------------------------------------------------------------
// Fused fp32 -> (hi,lo) bf16 split for all three tensors in ONE launch.
// ---------------------------------------------------------------------------
#define N4_X  (M_TOT*BC/4)
#define N4_QW (QKV_N*BC/4)
#define N4_PW (BC*BC/4)
#define N4_ALL (N4_X + N4_QW + N4_PW)

__global__ void split_all(const float4* __restrict__ x,
                          const float4* __restrict__ qw,
                          const float4* __restrict__ pw)
{
    int idx = blockIdx.x * blockDim.x + threadIdx.x;
    if (idx >= N4_ALL) return;

    const float4* src;
    __nv_bfloat16 *hi, *lo;
    int i;
    if (idx < N4_X)               { src = x;  hi = s_xh;  lo = s_xl;  i = idx; }
    else if (idx < N4_X + N4_QW)  { src = qw; hi = s_qwh; lo = s_qwl; i = idx - N4_X; }
    else                          { src = pw; hi = s_pwh; lo = s_pwl; i = idx - N4_X - N4_QW; }

    float4 v = src[i];
    float f[4] = {v.x, v.y, v.z, v.w};
    __nv_bfloat16 h[4], l[4];
    #pragma unroll
    for (int j = 0; j < 4; ++j) {
        h[j] = __float2bfloat16_rn(f[j]);
        l[j] = __float2bfloat16_rn(f[j] - __bfloat162float(h[j]));
    }
    __nv_bfloat162* hp = (__nv_bfloat162*)hi;
    __nv_bfloat162* lp = (__nv_bfloat162*)lo;
    hp[i*2+0] = __nv_bfloat162(h[0], h[1]);
    hp[i*2+1] = __nv_bfloat162(h[2], h[3]);
    lp[i*2+0] = __nv_bfloat162(l[0], l[1]);
    lp[i*2+1] = __nv_bfloat162(l[2], l[3]);
}

// ---------------------------------------------------------------------------
// PTX helpers
// ---------------------------------------------------------------------------
__device__ __forceinline__ void ldsm4(uint32_t& r0, uint32_t& r1,
                                      uint32_t& r2, uint32_t& r3, uint32_t a)
{
    asm volatile("ldmatrix.sync.aligned.m8n8.x4.shared.b16 {%0,%1,%2,%3},[%4];"
                 : "=r"(r0), "=r"(r1), "=r"(r2), "=r"(r3) : "r"(a));
}
__device__ __forceinline__ void mma16816(float& c0, float& c1, float& c2, float& c3,
                                         uint32_t a0, uint32_t a1, uint32_t a2, uint32_t a3,
                                         uint32_t b0, uint32_t b1)
{
    asm volatile("mma.sync.aligned.m16n8k16.row.col.f32.bf16.bf16.f32 "
                 "{%0,%1,%2,%3},{%4,%5,%6,%7},{%8,%9},{%0,%1,%2,%3};"
                 : "+f"(c0), "+f"(c1), "+f"(c2), "+f"(c3)
                 : "r"(a0), "r"(a1), "r"(a2), "r"(a3), "r"(b0), "r"(b1));
}
__device__ __forceinline__ void cp16(uint32_t d, const void* s)
{
    asm volatile("cp.async.cg.shared.global [%0],[%1],16;" :: "r"(d), "l"(s));
}
__device__ __forceinline__ void cp_commit() { asm volatile("cp.async.commit_group;"); }
template<int N>
__device__ __forceinline__ void cp_wait() { asm volatile("cp.async.wait_group %0;" :: "n"(N)); }

__device__ __forceinline__ uint32_t pack_bf2(float x, float y)
{
    __nv_bfloat162 t(__float2bfloat16_rn(x), __float2bfloat16_rn(y));
    return *(uint32_t*)&t;
}

// ---------------------------------------------------------------------------
// bf16x3 tensor-core GEMM, CTA tile 64x256 (same output count / MMA count /
// warp tile 32x64 / k-order as the 128x128 champion; only the CTA shape
// changes). M = 197*64 exactly -> NO tail, no zeroing, no predicates.
// Wave packing: gemm0 1773 CTAs <= 296*6 (6 waves, was 7);
//               gemm1  591 CTAs <= 296*2 (2 waves, was 3).
// MODE 0: A=s_x*, B=s_qw*, scatter -> g_q/g_k/g_v    MODE 1: A=s_o*, B=s_pw*
// ---------------------------------------------------------------------------
#define BM 64
#define BN 256
#define BKT 32
#define PCHB 80
#define A_TILE_B (64*PCHB)             // 5120
#define B_TILE_B (256*PCHB)            // 20480
#define OFF_AH 0
#define OFF_AL A_TILE_B                // 5120
#define OFF_BH (2*A_TILE_B)            // 10240
#define OFF_BL (2*A_TILE_B + B_TILE_B) // 30720
#define STAGE_B (2*A_TILE_B + 2*B_TILE_B)  // 51200
#define GEMM_SMEM (2*STAGE_B)          // 102400

template<int MODE>
__global__ __launch_bounds__(256, 2)
void gemm_tc(const float* __restrict__ bias, float* __restrict__ Cout, int Nn)
{
    const __nv_bfloat16* __restrict__ Ah = (MODE == 0) ? s_xh  : s_oh;
    const __nv_bfloat16* __restrict__ Al = (MODE == 0) ? s_xl  : s_ol;
    const __nv_bfloat16* __restrict__ Bh = (MODE == 0) ? s_qwh : s_pwh;
    const __nv_bfloat16* __restrict__ Bl = (MODE == 0) ? s_qwl : s_pwl;

    extern __shared__ char smem[];
    const uint32_t sb = (uint32_t)__cvta_generic_to_shared(smem);

    const int tid  = threadIdx.x;
    const int bm0  = blockIdx.y * BM;
    const int bn0  = blockIdx.x * BN;
    const int w    = tid >> 5;
    const int lane = tid & 31;
    const int wM   = w & 1;         // 2 strips of 32 rows
    const int wN   = w >> 1;        // 4 strips of 64 cols

    // loader mapping (no M guard needed: M is tile-exact)
    const int lrow = tid >> 2;      // 0..63
    const int lkc  = tid & 3;
    const uint32_t adoff = (uint32_t)(lrow * PCHB + lkc * 16);

    float acc[2][8][4];
    #pragma unroll
    for (int mt = 0; mt < 2; ++mt)
        #pragma unroll
        for (int nt = 0; nt < 8; ++nt)
            #pragma unroll
            for (int e = 0; e < 4; ++e) acc[mt][nt][e] = 0.f;

    auto load_stage = [&](int stage, int kt) {
        const int k0 = kt * BKT;
        const uint32_t base = sb + stage * STAGE_B;
        const int gcol = k0 + lkc * 8;
        // A: 64 rows, 1 chunk/thread per tensor
        {
            const size_t ao = (size_t)(bm0 + lrow) * KDIM + gcol;
            cp16(base + OFF_AH + adoff, Ah + ao);
            cp16(base + OFF_AL + adoff, Al + ao);
        }
        // B: 256 rows, 4 chunks/thread per tensor
        #pragma unroll
        for (int i = 0; i < 4; ++i) {
            const int row = lrow + (i << 6);
            const uint32_t doff = (uint32_t)(row * PCHB + lkc * 16);
            const size_t bo = (size_t)(bn0 + row) * KDIM + gcol;
            cp16(base + OFF_BH + doff, Bh + bo);
            cp16(base + OFF_BL + doff, Bl + bo);
        }
    };

    const int aRow  = wM * 32 + (lane & 15);
    const int bRow  = wN * 64 + (lane & 15);
    const int cSel  = lane >> 4;

    const int NK = KDIM / BKT;      // 24
    load_stage(0, 0);
    cp_commit();

    for (int kt = 0; kt < NK; ++kt) {
        cp_wait<0>();
        __syncthreads();
        if (kt + 1 < NK) {
            load_stage((kt + 1) & 1, kt + 1);
            cp_commit();
        }

        const uint32_t base = sb + (kt & 1) * STAGE_B;
        #pragma unroll
        for (int kk = 0; kk < 2; ++kk) {
            const int kb = kk * 2;
            uint32_t ah[2][4], al[2][4], bh[8][2], bl[8][2];
            #pragma unroll
            for (int mt = 0; mt < 2; ++mt) {
                const uint32_t ra = (aRow + mt * 16) * PCHB + (kb + cSel) * 16;
                ldsm4(ah[mt][0], ah[mt][1], ah[mt][2], ah[mt][3], base + OFF_AH + ra);
                ldsm4(al[mt][0], al[mt][1], al[mt][2], al[mt][3], base + OFF_AL + ra);
            }
            #pragma unroll
            for (int p = 0; p < 4; ++p) {
                const uint32_t rb = (bRow + p * 16) * PCHB + (kb + cSel) * 16;
                uint32_t t0, t1, t2, t3;
                ldsm4(t0, t1, t2, t3, base + OFF_BH + rb);
                bh[2*p][0] = t0; bh[2*p+1][0] = t1; bh[2*p][1] = t2; bh[2*p+1][1] = t3;
                ldsm4(t0, t1, t2, t3, base + OFF_BL + rb);
                bl[2*p][0] = t0; bl[2*p+1][0] = t1; bl[2*p][1] = t2; bl[2*p+1][1] = t3;
            }
            // product-major: hh, hl, lh (same per-accumulator order as champion)
            #pragma unroll
            for (int mt = 0; mt < 2; ++mt)
                #pragma unroll
                for (int nt = 0; nt < 8; ++nt) {
                    float* c = acc[mt][nt];
                    mma16816(c[0], c[1], c[2], c[3],
                             ah[mt][0], ah[mt][1], ah[mt][2], ah[mt][3],
                             bh[nt][0], bh[nt][1]);
                }
            #pragma unroll
            for (int mt = 0; mt < 2; ++mt)
                #pragma unroll
                for (int nt = 0; nt < 8; ++nt) {
                    float* c = acc[mt][nt];
                    mma16816(c[0], c[1], c[2], c[3],
                             ah[mt][0], ah[mt][1], ah[mt][2], ah[mt][3],
                             bl[nt][0], bl[nt][1]);
                }
            #pragma unroll
            for (int mt = 0; mt < 2; ++mt)
                #pragma unroll
                for (int nt = 0; nt < 8; ++nt) {
                    float* c = acc[mt][nt];
                    mma16816(c[0], c[1], c[2], c[3],
                             al[mt][0], al[mt][1], al[mt][2], al[mt][3],
                             bh[nt][0], bh[nt][1]);
                }
        }
    }

    const int mBase = bm0 + wM * 32 + (lane >> 2);
    const int nBase = bn0 + wN * 64 + ((lane & 3) << 1);
    #pragma unroll
    for (int mt = 0; mt < 2; ++mt) {
        #pragma unroll
        for (int half = 0; half < 2; ++half) {
            const int m = mBase + mt * 16 + half * 8;
            #pragma unroll
            for (int nt = 0; nt < 8; ++nt) {
                const int n = nBase + nt * 8;
                const float v0 = acc[mt][nt][half*2+0] + bias[n];
                const float v1 = acc[mt][nt][half*2+1] + bias[n+1];
                if (MODE == 0) {
                    const int b = m / SEQ;
                    const int t = m - b * SEQ;
                    #pragma unroll
                    for (int e = 0; e < 2; ++e) {
                        const int nn = n + e;
                        const float vv = e ? v1 : v0;
                        const int sel = nn / BC;
                        const int rr  = nn - sel * BC;
                        const int hh  = rr >> 6;
                        const int dd  = rr & 63;
                        float* dst = (sel == 0) ? g_q : (sel == 1) ? g_k : g_v;
                        dst[(((b * NH + hh) * SEQ + t) << 6) + dd] = vv;
                    }
                } else {
                    Cout[(size_t)m * Nn + n]     = v0;
                    Cout[(size_t)m * Nn + n + 1] = v1;
                }
            }
        }
    }
}

// ---------------------------------------------------------------------------
// Tensor-core attention (round-13 champion: 13 warps, pipelined j-loop,
// float4 fill, padding-only zeroing)
// ---------------------------------------------------------------------------
#define SEQP 208
#define AQ_PITCH 72
#define AV_PITCH 216
#define QH_OFF 0u
#define QL_OFF 29952u
#define KH_OFF 59904u
#define KL_OFF 89856u
#define VTH_OFF 119808u
#define VTL_OFF 147456u
#define ATTN_SMEM 175104
#define ATTN_THREADS 416

__global__ __launch_bounds__(ATTN_THREADS)
void attn_tc()
{
    extern __shared__ char asmem[];
    __nv_bfloat16* sb16 = (__nv_bfloat16*)asmem;
    const uint32_t sb = (uint32_t)__cvta_generic_to_shared(asmem);

    const int bh = blockIdx.x;
    const int b  = bh / NH;
    const int h  = bh - b * NH;
    const float* __restrict__ Qg = g_q + (size_t)bh * SEQ * HD;
    const float* __restrict__ Kg = g_k + (size_t)bh * SEQ * HD;
    const float* __restrict__ Vg = g_v + (size_t)bh * SEQ * HD;

    const int tid = threadIdx.x;

    for (int i = tid; i < 11 * HD; i += ATTN_THREADS) {
        const int t = SEQ + (i >> 6), d = i & 63;
        sb16[QH_OFF/2 + t*AQ_PITCH + d] = __nv_bfloat16(0.f);
        sb16[QL_OFF/2 + t*AQ_PITCH + d] = __nv_bfloat16(0.f);
        sb16[KH_OFF/2 + t*AQ_PITCH + d] = __nv_bfloat16(0.f);
        sb16[KL_OFF/2 + t*AQ_PITCH + d] = __nv_bfloat16(0.f);
    }
    for (int i = tid; i < HD * (AV_PITCH - SEQ); i += ATTN_THREADS) {
        const int d = i / (AV_PITCH - SEQ), t = SEQ + i % (AV_PITCH - SEQ);
        sb16[VTH_OFF/2 + d*AV_PITCH + t] = __nv_bfloat16(0.f);
        sb16[VTL_OFF/2 + d*AV_PITCH + t] = __nv_bfloat16(0.f);
    }
    __syncthreads();

    const float4* __restrict__ Qg4 = (const float4*)Qg;
    const float4* __restrict__ Kg4 = (const float4*)Kg;
    const float4* __restrict__ Vg4 = (const float4*)Vg;
    for (int i = tid; i < SEQ * HD / 4; i += ATTN_THREADS) {
        const int t = i >> 4;
        const int d0 = (i << 2) & 63;
        const float4 qv4 = Qg4[i];
        const float4 kv4 = Kg4[i];
        const float4 vv4 = Vg4[i];
        const float qf[4] = {qv4.x, qv4.y, qv4.z, qv4.w};
        const float kf[4] = {kv4.x, kv4.y, kv4.z, kv4.w};
        const float vf[4] = {vv4.x, vv4.y, vv4.z, vv4.w};
        #pragma unroll
        for (int e = 0; e < 4; ++e) {
            const int d = d0 + e;
            const float q = qf[e] * 0.125f;
            const __nv_bfloat16 qh = __float2bfloat16_rn(q);
            sb16[QH_OFF/2 + t*AQ_PITCH + d] = qh;
            sb16[QL_OFF/2 + t*AQ_PITCH + d] = __float2bfloat16_rn(q - __bfloat162float(qh));
            const float k = kf[e];
            const __nv_bfloat16 kh = __float2bfloat16_rn(k);
            sb16[KH_OFF/2 + t*AQ_PITCH + d] = kh;
            sb16[KL_OFF/2 + t*AQ_PITCH + d] = __float2bfloat16_rn(k - __bfloat162float(kh));
            const float v = vf[e];
            const __nv_bfloat16 vh = __float2bfloat16_rn(v);
            sb16[VTH_OFF/2 + d*AV_PITCH + t] = vh;
            sb16[VTL_OFF/2 + d*AV_PITCH + t] = __float2bfloat16_rn(v - __bfloat162float(vh));
        }
    }
    __syncthreads();

    const int w    = tid >> 5;
    const int lane = tid & 31;
    const int l15  = lane & 15;
    const int lhi  = lane >> 4;
    const int c2   = (lane & 3) << 1;
    const int r    = lane >> 2;

    const int m0 = w << 4;

    uint32_t aqh[4][4], aql[4][4];
    #pragma unroll
    for (int ks = 0; ks < 4; ++ks) {
        const uint32_t qa = sb + QH_OFF + (uint32_t)(m0 + l15) * 144u
                          + (uint32_t)((ks << 1) + lhi) * 16u;
        ldsm4(aqh[ks][0], aqh[ks][1], aqh[ks][2], aqh[ks][3], qa);
        ldsm4(aql[ks][0], aql[ks][1], aql[ks][2], aql[ks][3], qa + (QL_OFF - QH_OFF));
    }

    auto qk_tile = [&](int j, float* s) {
        #pragma unroll
        for (int e = 0; e < 8; ++e) s[e] = 0.f;
        #pragma unroll
        for (int ks = 0; ks < 4; ++ks) {
            const uint32_t ka = sb + KH_OFF + (uint32_t)((j << 4) + l15) * 144u
                              + (uint32_t)((ks << 1) + lhi) * 16u;
            uint32_t kh0,kh1,kh2,kh3, kl0,kl1,kl2,kl3;
            ldsm4(kh0,kh1,kh2,kh3, ka);
            ldsm4(kl0,kl1,kl2,kl3, ka + (KL_OFF - KH_OFF));
            mma16816(s[0],s[1],s[2],s[3],
                     aqh[ks][0],aqh[ks][1],aqh[ks][2],aqh[ks][3], kh0, kh2);
            mma16816(s[4],s[5],s[6],s[7],
                     aqh[ks][0],aqh[ks][1],aqh[ks][2],aqh[ks][3], kh1, kh3);
            mma16816(s[0],s[1],s[2],s[3],
                     aqh[ks][0],aqh[ks][1],aqh[ks][2],aqh[ks][3], kl0, kl2);
            mma16816(s[4],s[5],s[6],s[7],
                     aqh[ks][0],aqh[ks][1],aqh[ks][2],aqh[ks][3], kl1, kl3);
            mma16816(s[0],s[1],s[2],s[3],
                     aql[ks][0],aql[ks][1],aql[ks][2],aql[ks][3], kh0, kh2);
            mma16816(s[4],s[5],s[6],s[7],
                     aql[ks][0],aql[ks][1],aql[ks][2],aql[ks][3], kh1, kh3);
        }
    };

    float o[8][4];
    #pragma unroll
    for (int t = 0; t < 8; ++t)
        #pragma unroll
        for (int e = 0; e < 4; ++e) o[t][e] = 0.f;
    float ls0 = 0.f, ls1 = 0.f;

    float scur[8];
    qk_tile(0, scur);

    for (int j = 0; j < 13; ++j) {
        float snxt[8];
        if (j < 12) qk_tile(j + 1, snxt);

        const int kb = (j << 4) + c2;
        const bool v0 = (kb     < SEQ), v1 = (kb + 1 < SEQ);
        const bool v8 = (kb + 8 < SEQ), v9 = (kb + 9 < SEQ);
        const float p00 = v0 ? __expf(scur[0]) : 0.f;
        const float p01 = v1 ? __expf(scur[1]) : 0.f;
        const float p02 = v0 ? __expf(scur[2]) : 0.f;
        const float p03 = v1 ? __expf(scur[3]) : 0.f;
        const float p10 = v8 ? __expf(scur[4]) : 0.f;
        const float p11 = v9 ? __expf(scur[5]) : 0.f;
        const float p12 = v8 ? __expf(scur[6]) : 0.f;
        const float p13 = v9 ? __expf(scur[7]) : 0.f;
        ls0 += (p00 + p01) + (p10 + p11);
        ls1 += (p02 + p03) + (p12 + p13);

        const float h00 = __bfloat162float(__float2bfloat16_rn(p00));
        const float h01 = __bfloat162float(__float2bfloat16_rn(p01));
        const float h02 = __bfloat162float(__float2bfloat16_rn(p02));
        const float h03 = __bfloat162float(__float2bfloat16_rn(p03));
        const float h10 = __bfloat162float(__float2bfloat16_rn(p10));
        const float h11 = __bfloat162float(__float2bfloat16_rn(p11));
        const float h12 = __bfloat162float(__float2bfloat16_rn(p12));
        const float h13 = __bfloat162float(__float2bfloat16_rn(p13));
        uint32_t pah[4], pal[4];
        pah[0] = pack_bf2(h00, h01); pal[0] = pack_bf2(p00 - h00, p01 - h01);
        pah[1] = pack_bf2(h02, h03); pal[1] = pack_bf2(p02 - h02, p03 - h03);
        pah[2] = pack_bf2(h10, h11); pal[2] = pack_bf2(p10 - h10, p11 - h11);
        pah[3] = pack_bf2(h12, h13); pal[3] = pack_bf2(p12 - h12, p13 - h13);

        #pragma unroll
        for (int g = 0; g < 4; ++g) {
            const uint32_t va = sb + VTH_OFF + (uint32_t)((g << 4) + l15) * 432u
                              + (uint32_t)((j << 1) + lhi) * 16u;
            uint32_t vh0,vh1,vh2,vh3, vl0,vl1,vl2,vl3;
            ldsm4(vh0,vh1,vh2,vh3, va);
            ldsm4(vl0,vl1,vl2,vl3, va + (VTL_OFF - VTH_OFF));
            float* oa = o[g*2];
            float* ob = o[g*2+1];
            mma16816(oa[0],oa[1],oa[2],oa[3], pah[0],pah[1],pah[2],pah[3], vh0, vh2);
            mma16816(ob[0],ob[1],ob[2],ob[3], pah[0],pah[1],pah[2],pah[3], vh1, vh3);
            mma16816(oa[0],oa[1],oa[2],oa[3], pah[0],pah[1],pah[2],pah[3], vl0, vl2);
            mma16816(ob[0],ob[1],ob[2],ob[3], pah[0],pah[1],pah[2],pah[3], vl1, vl3);
            mma16816(oa[0],oa[1],oa[2],oa[3], pal[0],pal[1],pal[2],pal[3], vh0, vh2);
            mma16816(ob[0],ob[1],ob[2],ob[3], pal[0],pal[1],pal[2],pal[3], vh1, vh3);
        }

        #pragma unroll
        for (int e = 0; e < 8; ++e) scur[e] = snxt[e];
    }

    ls0 += __shfl_xor_sync(0xffffffffu, ls0, 1);
    ls0 += __shfl_xor_sync(0xffffffffu, ls0, 2);
    ls1 += __shfl_xor_sync(0xffffffffu, ls1, 1);
    ls1 += __shfl_xor_sync(0xffffffffu, ls1, 2);
    const float inv0 = 1.f / ls0;
    const float inv1 = 1.f / ls1;

    const int row0 = m0 + r;
    const int row1 = row0 + 8;
    #pragma unroll
    for (int t = 0; t < 8; ++t) {
        const int d = h * HD + t * 8 + c2;
        if (row0 < SEQ) {
            const size_t base = (size_t)(b * SEQ + row0) * BC + d;
            const float y0 = o[t][0] * inv0, y1 = o[t][1] * inv0;
            const __nv_bfloat16 yh0 = __float2bfloat16_rn(y0);
            const __nv_bfloat16 yh1 = __float2bfloat16_rn(y1);
            s_oh[base]   = yh0;
            s_oh[base+1] = yh1;
            s_ol[base]   = __float2bfloat16_rn(y0 - __bfloat162float(yh0));
            s_ol[base+1] = __float2bfloat16_rn(y1 - __bfloat162float(yh1));
        }
        if (row1 < SEQ) {
            const size_t base = (size_t)(b * SEQ + row1) * BC + d;
            const float y0 = o[t][2] * inv1, y1 = o[t][3] * inv1;
            const __nv_bfloat16 yh0 = __float2bfloat16_rn(y0);
            const __nv_bfloat16 yh1 = __float2bfloat16_rn(y1);
            s_oh[base]   = yh0;
            s_oh[base+1] = yh1;
            s_ol[base]   = __float2bfloat16_rn(y0 - __bfloat162float(yh0));
            s_ol[base+1] = __float2bfloat16_rn(y1 - __bfloat162float(yh1));
        }
    }
}

// ---------------------------------------------------------------------------
extern "C" void kernel_launch(void* const* d_in, const int* in_sizes, int n_in,
                              void* d_out, int out_size)
{
    const float* x  = (const float*)d_in[0];
    const float* qw = (const float*)d_in[1];
    const float* qb = (const float*)d_in[2];
    const float* pw = (const float*)d_in[3];
    const float* pb = (const float*)d_in[4];
    float* out = (float*)d_out;

    // smoothquant power-of-2 channel scaling cancels bit-exactly in fp32: skipped.

    cudaFuncSetAttribute(attn_tc,
                         cudaFuncAttributeMaxDynamicSharedMemorySize, ATTN_SMEM);
    cudaFuncSetAttribute(gemm_tc<0>,
                         cudaFuncAttributeMaxDynamicSharedMemorySize, GEMM_SMEM);
    cudaFuncSetAttribute(gemm_tc<1>,
                         cudaFuncAttributeMaxDynamicSharedMemorySize, GEMM_SMEM);

    split_all<<<(N4_ALL + 255) / 256, 256>>>((const float4*)x, (const float4*)qw,
                                             (const float4*)pw);

    dim3 g1(QKV_N / BN, M_TOT / BM);   // 9 x 197 = 1773 CTAs (6 full waves)
    gemm_tc<0><<<g1, 256, GEMM_SMEM>>>(qb, nullptr, QKV_N);

    attn_tc<<<BATCH * NH, ATTN_THREADS, ATTN_SMEM>>>();

    dim3 g2(BC / BN, M_TOT / BM);      // 3 x 197 = 591 CTAs (2 full waves)
    gemm_tc<1><<<g2, 256, GEMM_SMEM>>>(pb, out, BC);
}